// round 3
// baseline (speedup 1.0000x reference)
#include <cuda_runtime.h>
#include <math.h>

#define TBL    524288u                 // T = 2^19 entries per level
#define MASK8  ((TBL - 1u) * 8u)       // byte-space mask: 0x3FFFF8
#define MASK16 (MASK8 & ~8u)           // 16B-aligned byte mask: 0x3FFFF0
#define PR1    2654435761u
#define PR2    805459861u

#define NPTS   2097152u
#define BX     16                      // spatial buckets per axis
#define NBKT   (BX * BX * BX)          // 4096 buckets

struct Res16 { int r[16]; };

// ---- device scratch (static allocation only; no cudaMalloc allowed) ----
__device__ unsigned g_hist[NBKT];
__device__ unsigned g_base[NBKT + 1];
__device__ unsigned g_cursor[NBKT];
__device__ unsigned g_perm[NPTS];        // sorted slot -> original point id
__device__ float4   g_xs[NPTS];          // sorted coords (w unused)

__device__ __forceinline__ float2 lerp2(float2 a, float2 b, float t) {
    return make_float2(fmaf(t, b.x - a.x, a.x), fmaf(t, b.y - a.y, a.y));
}

template<bool CG>
__device__ __forceinline__ float2 ld8(const char* p) {
    return CG ? __ldcg((const float2*)p) : __ldg((const float2*)p);
}
template<bool CG>
__device__ __forceinline__ float4 ld16(const char* p) {
    return CG ? __ldcg((const float4*)p) : __ldg((const float4*)p);
}

// One level of hash-grid trilinear interpolation. Hash math in byte-offset
// space. For EVEN ix the two x-corners share one aligned 16B block -> one
// LDG.128. CG=true routes loads L2-only (fine levels: no reuse -> don't
// evict the coarse-level L1 working set).
template<bool CG>
__device__ __forceinline__ float2 enc_level(
    const char* __restrict__ base, float px, float py, float pz, float r)
{
    float xs = px * r, ys = py * r, zs = pz * r;
    int ix = (int)xs, iy = (int)ys, iz = (int)zs;
    float fx = xs - (float)ix;
    float fy = ys - (float)iy;
    float fz = zs - (float)iz;

    unsigned hx0 = ((unsigned)ix) << 3;
    unsigned hy0 = (unsigned)iy * (PR1 * 8u);
    unsigned hy1 = hy0 + (PR1 * 8u);
    unsigned hz0 = (unsigned)iz * (PR2 * 8u);
    unsigned hz1 = hz0 + (PR2 * 8u);
    unsigned a00 = hy0 ^ hz0;
    unsigned a01 = hy0 ^ hz1;
    unsigned a10 = hy1 ^ hz0;
    unsigned a11 = hy1 ^ hz1;

    float2 e000, e001, e010, e011, e100, e101, e110, e111;

    if ((hx0 & 8u) == 0u) {
        float4 v00 = ld16<CG>(base + ((hx0 ^ a00) & MASK16));
        float4 v01 = ld16<CG>(base + ((hx0 ^ a01) & MASK16));
        float4 v10 = ld16<CG>(base + ((hx0 ^ a10) & MASK16));
        float4 v11 = ld16<CG>(base + ((hx0 ^ a11) & MASK16));
        bool s00 = (a00 & 8u) != 0u;
        bool s01 = (a01 & 8u) != 0u;
        bool s10 = (a10 & 8u) != 0u;
        bool s11 = (a11 & 8u) != 0u;
        e000 = s00 ? make_float2(v00.z, v00.w) : make_float2(v00.x, v00.y);
        e100 = s00 ? make_float2(v00.x, v00.y) : make_float2(v00.z, v00.w);
        e001 = s01 ? make_float2(v01.z, v01.w) : make_float2(v01.x, v01.y);
        e101 = s01 ? make_float2(v01.x, v01.y) : make_float2(v01.z, v01.w);
        e010 = s10 ? make_float2(v10.z, v10.w) : make_float2(v10.x, v10.y);
        e110 = s10 ? make_float2(v10.x, v10.y) : make_float2(v10.z, v10.w);
        e011 = s11 ? make_float2(v11.z, v11.w) : make_float2(v11.x, v11.y);
        e111 = s11 ? make_float2(v11.x, v11.y) : make_float2(v11.z, v11.w);
    } else {
        unsigned hx1 = hx0 + 8u;
        e000 = ld8<CG>(base + ((hx0 ^ a00) & MASK8));
        e001 = ld8<CG>(base + ((hx0 ^ a01) & MASK8));
        e010 = ld8<CG>(base + ((hx0 ^ a10) & MASK8));
        e011 = ld8<CG>(base + ((hx0 ^ a11) & MASK8));
        e100 = ld8<CG>(base + ((hx1 ^ a00) & MASK8));
        e101 = ld8<CG>(base + ((hx1 ^ a01) & MASK8));
        e110 = ld8<CG>(base + ((hx1 ^ a10) & MASK8));
        e111 = ld8<CG>(base + ((hx1 ^ a11) & MASK8));
    }

    float2 c00 = lerp2(e000, e100, fx);
    float2 c01 = lerp2(e001, e101, fx);
    float2 c10 = lerp2(e010, e110, fx);
    float2 c11 = lerp2(e011, e111, fx);
    float2 c0  = lerp2(c00, c10, fy);
    float2 c1  = lerp2(c01, c11, fy);
    return lerp2(c0, c1, fz);
}

__device__ __forceinline__ int bucket_of(float px, float py, float pz) {
    int bx = min((int)(px * (float)BX), BX - 1);
    int by = min((int)(py * (float)BX), BX - 1);
    int bz = min((int)(pz * (float)BX), BX - 1);
    return (bz * BX + by) * BX + bx;
}

// ---- sort pipeline ----
__global__ void zero_hist_kernel() {
    unsigned i = blockIdx.x * blockDim.x + threadIdx.x;
    if (i < NBKT) g_hist[i] = 0u;
}

__global__ void hist_kernel(const float* __restrict__ x, unsigned npts) {
    unsigned i = blockIdx.x * blockDim.x + threadIdx.x;
    if (i >= npts) return;
    float px = x[3u * i], py = x[3u * i + 1u], pz = x[3u * i + 2u];
    atomicAdd(&g_hist[bucket_of(px, py, pz)], 1u);
}

__global__ void scan_kernel() {   // single block, 1024 threads, 4 buckets each
    __shared__ unsigned s[1024];
    unsigned t = threadIdx.x;
    unsigned v0 = g_hist[4u * t + 0u];
    unsigned v1 = g_hist[4u * t + 1u];
    unsigned v2 = g_hist[4u * t + 2u];
    unsigned v3 = g_hist[4u * t + 3u];
    unsigned sum = v0 + v1 + v2 + v3;
    s[t] = sum;
    __syncthreads();
    for (unsigned off = 1u; off < 1024u; off <<= 1) {   // Hillis-Steele inclusive
        unsigned add = (t >= off) ? s[t - off] : 0u;
        __syncthreads();
        s[t] += add;
        __syncthreads();
    }
    unsigned excl = s[t] - sum;
    unsigned b0 = excl, b1 = excl + v0, b2 = b1 + v1, b3 = b2 + v2;
    g_base[4u * t + 0u] = b0;  g_cursor[4u * t + 0u] = b0;
    g_base[4u * t + 1u] = b1;  g_cursor[4u * t + 1u] = b1;
    g_base[4u * t + 2u] = b2;  g_cursor[4u * t + 2u] = b2;
    g_base[4u * t + 3u] = b3;  g_cursor[4u * t + 3u] = b3;
    if (t == 1023u) g_base[NBKT] = s[1023u];
}

__global__ void scatter_kernel(const float* __restrict__ x, unsigned npts) {
    unsigned i = blockIdx.x * blockDim.x + threadIdx.x;
    if (i >= npts) return;
    float px = x[3u * i], py = x[3u * i + 1u], pz = x[3u * i + 2u];
    unsigned pos = atomicAdd(&g_cursor[bucket_of(px, py, pz)], 1u);
    g_perm[pos] = i;
    g_xs[pos] = make_float4(px, py, pz, 0.0f);
}

// ---- encode: one 1024-thread CTA per bucket; 1 CTA/SM (register-limited),
// so L1 holds exactly one bucket's coarse working set. 8 threads per point,
// 2 levels per thread, float4 output per thread at the point's ORIGINAL slot.
__global__ void __launch_bounds__(1024, 1) encode_sorted_kernel(
    const float* __restrict__ emb,
    float* __restrict__ out,
    Res16 rr)
{
    unsigned b = blockIdx.x;
    unsigned start = g_base[b];
    unsigned end   = g_base[b + 1u];
    unsigned tid = threadIdx.x;
    unsigned chunk = tid & 7u;
    unsigned lvl = chunk * 2u;

    const char* base0 = (const char*)emb + (size_t)lvl * (size_t)(TBL * 8u);
    const char* base1 = base0 + (size_t)(TBL * 8u);
    float r0 = (float)rr.r[lvl];
    float r1 = (float)rr.r[lvl + 1u];

    for (unsigned idx = start + (tid >> 3); idx < end; idx += 128u) {
        float4 p = g_xs[idx];
        unsigned pidx = g_perm[idx];

        float2 f0, f1;
        if (chunk < 3u) {                       // levels 0..5: L1-cached
            f0 = enc_level<false>(base0, p.x, p.y, p.z, r0);
            f1 = enc_level<false>(base1, p.x, p.y, p.z, r1);
        } else if (chunk == 3u) {               // level 6 cached, 7 L2-only
            f0 = enc_level<false>(base0, p.x, p.y, p.z, r0);
            f1 = enc_level<true >(base1, p.x, p.y, p.z, r1);
        } else {                                // levels 8..15: L2-only
            f0 = enc_level<true >(base0, p.x, p.y, p.z, r0);
            f1 = enc_level<true >(base1, p.x, p.y, p.z, r1);
        }

        float4 o = make_float4(f0.x, f0.y, f1.x, f1.y);
        *(float4*)(out + (size_t)pidx * 32u + chunk * 4u) = o;
    }
}

// ---- fallback (unsorted) for unexpected sizes ----
__global__ void __launch_bounds__(256, 4) hashenc_fallback_kernel(
    const float* __restrict__ x,
    const float* __restrict__ emb,
    float* __restrict__ out,
    unsigned npts, Res16 rr)
{
    unsigned tid = blockIdx.x * 256u + threadIdx.x;
    unsigned pt = tid >> 3;
    if (pt >= npts) return;
    unsigned chunk = tid & 7u;
    unsigned lvl = chunk * 2u;

    float px = __ldg(x + 3u * pt + 0u);
    float py = __ldg(x + 3u * pt + 1u);
    float pz = __ldg(x + 3u * pt + 2u);

    const char* base0 = (const char*)emb + (size_t)lvl * (size_t)(TBL * 8u);
    float r0 = (float)rr.r[lvl];
    float r1 = (float)rr.r[lvl + 1u];

    float2 f0 = enc_level<false>(base0, px, py, pz, r0);
    float2 f1 = enc_level<false>(base0 + (size_t)(TBL * 8u), px, py, pz, r1);

    float4 o = make_float4(f0.x, f0.y, f1.x, f1.y);
    *(float4*)(out + (size_t)pt * 32u + chunk * 4u) = o;
}

extern "C" void kernel_launch(void* const* d_in, const int* in_sizes, int n_in,
                              void* d_out, int out_size)
{
    const float* x   = (const float*)d_in[0];   // [2097152, 3] f32
    const float* emb = (const float*)d_in[1];   // [16, 524288, 2] f32
    float* out = (float*)d_out;                 // [2097152, 32] f32

    unsigned npts = (unsigned)(in_sizes[0] / 3);

    // Resolutions via the exact reference formula in double precision
    // (floor margins as small as 0.004 at level 14 -> do NOT hardcode).
    Res16 rr;
    double b = exp((log(2048.0) - log(16.0)) / 15.0);
    for (int i = 0; i < 16; i++)
        rr.r[i] = (int)floor(16.0 * pow(b, (double)i));

    if (npts == NPTS) {
        unsigned blocks = (npts + 255u) / 256u;
        zero_hist_kernel<<<(NBKT + 255u) / 256u, 256>>>();
        hist_kernel<<<blocks, 256>>>(x, npts);
        scan_kernel<<<1, 1024>>>();
        scatter_kernel<<<blocks, 256>>>(x, npts);
        encode_sorted_kernel<<<NBKT, 1024>>>(emb, out, rr);
    } else {
        unsigned total = npts * 8u;
        hashenc_fallback_kernel<<<(total + 255u) / 256u, 256>>>(x, emb, out, npts, rr);
    }
}

// round 4
// speedup vs baseline: 1.3019x; 1.3019x over previous
#include <cuda_runtime.h>
#include <math.h>

#define TBL    524288u                 // T = 2^19 entries per level
#define MASK8  ((TBL - 1u) * 8u)       // byte-space mask
#define MASK16 (MASK8 & ~8u)           // 16B-aligned byte mask
#define PR1    2654435761u
#define PR2    805459861u

#define NPTS   2097152u
#define BX     32                      // spatial buckets per axis
#define NBKT   (BX * BX * BX)          // 32768 buckets (~64 pts each)

struct Res16 { int r[16]; };

// ---- device scratch (static only; no cudaMalloc allowed) ----
__device__ unsigned g_hist[NBKT];
__device__ unsigned g_base[NBKT + 1];
__device__ unsigned g_cursor[NBKT];
__device__ unsigned g_perm[NPTS];        // sorted slot -> original point id
__device__ float4   g_xs[NPTS];          // sorted coords (w unused)

__device__ __forceinline__ float2 lerp2(float2 a, float2 b, float t) {
    return make_float2(fmaf(t, b.x - a.x, a.x), fmaf(t, b.y - a.y, a.y));
}

template<bool CG>
__device__ __forceinline__ float2 ld8(const char* p) {
    return CG ? __ldcg((const float2*)p) : __ldg((const float2*)p);
}
template<bool CG>
__device__ __forceinline__ float4 ld16(const char* p) {
    return CG ? __ldcg((const float4*)p) : __ldg((const float4*)p);
}

// One level of hash-grid trilinear interpolation; byte-space hashing.
// EVEN ix: both x-corners sit in one aligned 16B block -> single LDG.128.
// CG=true routes the load L2-only (fine levels: no reuse, keep L1 clean).
template<bool CG>
__device__ __forceinline__ float2 enc_level(
    const char* __restrict__ base, float px, float py, float pz, float r)
{
    float xs = px * r, ys = py * r, zs = pz * r;
    int ix = (int)xs, iy = (int)ys, iz = (int)zs;
    float fx = xs - (float)ix;
    float fy = ys - (float)iy;
    float fz = zs - (float)iz;

    unsigned hx0 = ((unsigned)ix) << 3;
    unsigned hy0 = (unsigned)iy * (PR1 * 8u);
    unsigned hy1 = hy0 + (PR1 * 8u);
    unsigned hz0 = (unsigned)iz * (PR2 * 8u);
    unsigned hz1 = hz0 + (PR2 * 8u);
    unsigned a00 = hy0 ^ hz0;
    unsigned a01 = hy0 ^ hz1;
    unsigned a10 = hy1 ^ hz0;
    unsigned a11 = hy1 ^ hz1;

    float2 e000, e001, e010, e011, e100, e101, e110, e111;

    if ((hx0 & 8u) == 0u) {
        float4 v00 = ld16<CG>(base + ((hx0 ^ a00) & MASK16));
        float4 v01 = ld16<CG>(base + ((hx0 ^ a01) & MASK16));
        float4 v10 = ld16<CG>(base + ((hx0 ^ a10) & MASK16));
        float4 v11 = ld16<CG>(base + ((hx0 ^ a11) & MASK16));
        bool s00 = (a00 & 8u) != 0u;
        bool s01 = (a01 & 8u) != 0u;
        bool s10 = (a10 & 8u) != 0u;
        bool s11 = (a11 & 8u) != 0u;
        e000 = s00 ? make_float2(v00.z, v00.w) : make_float2(v00.x, v00.y);
        e100 = s00 ? make_float2(v00.x, v00.y) : make_float2(v00.z, v00.w);
        e001 = s01 ? make_float2(v01.z, v01.w) : make_float2(v01.x, v01.y);
        e101 = s01 ? make_float2(v01.x, v01.y) : make_float2(v01.z, v01.w);
        e010 = s10 ? make_float2(v10.z, v10.w) : make_float2(v10.x, v10.y);
        e110 = s10 ? make_float2(v10.x, v10.y) : make_float2(v10.z, v10.w);
        e011 = s11 ? make_float2(v11.z, v11.w) : make_float2(v11.x, v11.y);
        e111 = s11 ? make_float2(v11.x, v11.y) : make_float2(v11.z, v11.w);
    } else {
        unsigned hx1 = hx0 + 8u;
        e000 = ld8<CG>(base + ((hx0 ^ a00) & MASK8));
        e001 = ld8<CG>(base + ((hx0 ^ a01) & MASK8));
        e010 = ld8<CG>(base + ((hx0 ^ a10) & MASK8));
        e011 = ld8<CG>(base + ((hx0 ^ a11) & MASK8));
        e100 = ld8<CG>(base + ((hx1 ^ a00) & MASK8));
        e101 = ld8<CG>(base + ((hx1 ^ a01) & MASK8));
        e110 = ld8<CG>(base + ((hx1 ^ a10) & MASK8));
        e111 = ld8<CG>(base + ((hx1 ^ a11) & MASK8));
    }

    float2 c00 = lerp2(e000, e100, fx);
    float2 c01 = lerp2(e001, e101, fx);
    float2 c10 = lerp2(e010, e110, fx);
    float2 c11 = lerp2(e011, e111, fx);
    float2 c0  = lerp2(c00, c10, fy);
    float2 c1  = lerp2(c01, c11, fy);
    return lerp2(c0, c1, fz);
}

__device__ __forceinline__ int bucket_of(float px, float py, float pz) {
    int bx = min((int)(px * (float)BX), BX - 1);
    int by = min((int)(py * (float)BX), BX - 1);
    int bz = min((int)(pz * (float)BX), BX - 1);
    return (bz * BX + by) * BX + bx;
}

// ---- sort pipeline ----
__global__ void zero_hist_kernel() {
    unsigned i = blockIdx.x * blockDim.x + threadIdx.x;
    if (i < NBKT) g_hist[i] = 0u;
}

__global__ void hist_kernel(const float* __restrict__ x, unsigned npts) {
    unsigned i = blockIdx.x * blockDim.x + threadIdx.x;
    if (i >= npts) return;
    float px = x[3u * i], py = x[3u * i + 1u], pz = x[3u * i + 2u];
    atomicAdd(&g_hist[bucket_of(px, py, pz)], 1u);
}

// single block, 1024 threads, 32 buckets each (serial) + block scan
__global__ void scan_kernel() {
    __shared__ unsigned s[1024];
    unsigned t = threadIdx.x;
    unsigned v[32];
    unsigned sum = 0u;
    #pragma unroll
    for (int j = 0; j < 32; j++) { v[j] = g_hist[32u * t + j]; sum += v[j]; }
    s[t] = sum;
    __syncthreads();
    for (unsigned off = 1u; off < 1024u; off <<= 1) {   // Hillis-Steele inclusive
        unsigned add = (t >= off) ? s[t - off] : 0u;
        __syncthreads();
        s[t] += add;
        __syncthreads();
    }
    unsigned run = s[t] - sum;                           // exclusive base
    #pragma unroll
    for (int j = 0; j < 32; j++) {
        g_base[32u * t + j]   = run;
        g_cursor[32u * t + j] = run;
        run += v[j];
    }
    if (t == 1023u) g_base[NBKT] = s[1023u];
}

__global__ void scatter_kernel(const float* __restrict__ x, unsigned npts) {
    unsigned i = blockIdx.x * blockDim.x + threadIdx.x;
    if (i >= npts) return;
    float px = x[3u * i], py = x[3u * i + 1u], pz = x[3u * i + 2u];
    unsigned pos = atomicAdd(&g_cursor[bucket_of(px, py, pz)], 1u);
    g_perm[pos] = i;
    g_xs[pos] = make_float4(px, py, pz, 0.0f);
}

// ---- encode: one 256-thread CTA per bucket (~64 pts). 8 threads/point,
// 2 levels per thread. Levels 0-8 L1-cached (per-bucket footprint ~11KB;
// 6 CTAs/SM -> ~68KB < L1), levels 9-15 L2-only.
__global__ void __launch_bounds__(256, 6) encode_sorted_kernel(
    const float* __restrict__ emb,
    float* __restrict__ out,
    Res16 rr)
{
    unsigned b = blockIdx.x;
    unsigned start = g_base[b];
    unsigned end   = g_base[b + 1u];
    unsigned tid = threadIdx.x;
    unsigned chunk = tid & 7u;
    unsigned lvl = chunk * 2u;

    const char* base0 = (const char*)emb + (size_t)lvl * (size_t)(TBL * 8u);
    const char* base1 = base0 + (size_t)(TBL * 8u);
    float r0 = (float)rr.r[lvl];
    float r1 = (float)rr.r[lvl + 1u];

    for (unsigned idx = start + (tid >> 3); idx < end; idx += 32u) {
        float4 p = g_xs[idx];
        unsigned pidx = g_perm[idx];

        float2 f0, f1;
        if (chunk < 4u) {                       // levels 0..7: L1-cached
            f0 = enc_level<false>(base0, p.x, p.y, p.z, r0);
            f1 = enc_level<false>(base1, p.x, p.y, p.z, r1);
        } else if (chunk == 4u) {               // level 8 cached, 9 L2-only
            f0 = enc_level<false>(base0, p.x, p.y, p.z, r0);
            f1 = enc_level<true >(base1, p.x, p.y, p.z, r1);
        } else {                                // levels 10..15: L2-only
            f0 = enc_level<true >(base0, p.x, p.y, p.z, r0);
            f1 = enc_level<true >(base1, p.x, p.y, p.z, r1);
        }

        float4 o = make_float4(f0.x, f0.y, f1.x, f1.y);
        *(float4*)(out + (size_t)pidx * 32u + chunk * 4u) = o;
    }
}

// ---- fallback (unsorted) for unexpected sizes ----
__global__ void __launch_bounds__(256, 4) hashenc_fallback_kernel(
    const float* __restrict__ x,
    const float* __restrict__ emb,
    float* __restrict__ out,
    unsigned npts, Res16 rr)
{
    unsigned tid = blockIdx.x * 256u + threadIdx.x;
    unsigned pt = tid >> 3;
    if (pt >= npts) return;
    unsigned chunk = tid & 7u;
    unsigned lvl = chunk * 2u;

    float px = __ldg(x + 3u * pt + 0u);
    float py = __ldg(x + 3u * pt + 1u);
    float pz = __ldg(x + 3u * pt + 2u);

    const char* base0 = (const char*)emb + (size_t)lvl * (size_t)(TBL * 8u);
    float r0 = (float)rr.r[lvl];
    float r1 = (float)rr.r[lvl + 1u];

    float2 f0 = enc_level<false>(base0, px, py, pz, r0);
    float2 f1 = enc_level<false>(base0 + (size_t)(TBL * 8u), px, py, pz, r1);

    float4 o = make_float4(f0.x, f0.y, f1.x, f1.y);
    *(float4*)(out + (size_t)pt * 32u + chunk * 4u) = o;
}

extern "C" void kernel_launch(void* const* d_in, const int* in_sizes, int n_in,
                              void* d_out, int out_size)
{
    const float* x   = (const float*)d_in[0];   // [2097152, 3] f32
    const float* emb = (const float*)d_in[1];   // [16, 524288, 2] f32
    float* out = (float*)d_out;                 // [2097152, 32] f32

    unsigned npts = (unsigned)(in_sizes[0] / 3);

    // Resolutions via the exact reference formula in double precision
    // (floor margins as small as 0.004 -> do NOT hardcode).
    Res16 rr;
    double b = exp((log(2048.0) - log(16.0)) / 15.0);
    for (int i = 0; i < 16; i++)
        rr.r[i] = (int)floor(16.0 * pow(b, (double)i));

    if (npts == NPTS) {
        unsigned blocks = (npts + 255u) / 256u;
        zero_hist_kernel<<<(NBKT + 255u) / 256u, 256>>>();
        hist_kernel<<<blocks, 256>>>(x, npts);
        scan_kernel<<<1, 1024>>>();
        scatter_kernel<<<blocks, 256>>>(x, npts);
        encode_sorted_kernel<<<NBKT, 256>>>(emb, out, rr);
    } else {
        unsigned total = npts * 8u;
        hashenc_fallback_kernel<<<(total + 255u) / 256u, 256>>>(x, emb, out, npts, rr);
    }
}

// round 5
// speedup vs baseline: 1.6238x; 1.2473x over previous
#include <cuda_runtime.h>
#include <math.h>

#define TBL    524288u                 // T = 2^19 entries per level
#define MASK8  ((TBL - 1u) * 8u)       // byte-space mask
#define MASK16 (MASK8 & ~8u)           // 16B-aligned byte mask
#define PR1    2654435761u
#define PR2    805459861u

#define NPTS   2097152u
#define BX     32                      // spatial buckets per axis
#define NBKT   (BX * BX * BX)          // 32768 buckets (~64 pts each)

struct Res16 { int r[16]; };

// ---- device scratch (static only; no cudaMalloc allowed) ----
__device__ unsigned g_hist[NBKT];
__device__ unsigned g_cursor[NBKT];
__device__ unsigned g_perm[NPTS];        // sorted slot -> original point id

__device__ __forceinline__ float2 lerp2(float2 a, float2 b, float t) {
    return make_float2(fmaf(t, b.x - a.x, a.x), fmaf(t, b.y - a.y, a.y));
}

// One level of hash-grid trilinear interpolation; byte-space hashing.
// EVEN ix: both x-corners sit in one aligned 16B block -> single LDG.128.
// All 32 lanes of a warp run the same level on spatially adjacent points,
// so lanes whose corners fall in the same 128B line merge into one l1tex
// wavefront (the binding resource).
__device__ __forceinline__ float2 enc_level(
    const char* __restrict__ base, float px, float py, float pz, float r)
{
    float xs = px * r, ys = py * r, zs = pz * r;
    int ix = (int)xs, iy = (int)ys, iz = (int)zs;
    float fx = xs - (float)ix;
    float fy = ys - (float)iy;
    float fz = zs - (float)iz;

    unsigned hx0 = ((unsigned)ix) << 3;
    unsigned hy0 = (unsigned)iy * (PR1 * 8u);
    unsigned hy1 = hy0 + (PR1 * 8u);
    unsigned hz0 = (unsigned)iz * (PR2 * 8u);
    unsigned hz1 = hz0 + (PR2 * 8u);
    unsigned a00 = hy0 ^ hz0;
    unsigned a01 = hy0 ^ hz1;
    unsigned a10 = hy1 ^ hz0;
    unsigned a11 = hy1 ^ hz1;

    float2 e000, e001, e010, e011, e100, e101, e110, e111;

    if ((hx0 & 8u) == 0u) {
        float4 v00 = __ldg((const float4*)(base + ((hx0 ^ a00) & MASK16)));
        float4 v01 = __ldg((const float4*)(base + ((hx0 ^ a01) & MASK16)));
        float4 v10 = __ldg((const float4*)(base + ((hx0 ^ a10) & MASK16)));
        float4 v11 = __ldg((const float4*)(base + ((hx0 ^ a11) & MASK16)));
        bool s00 = (a00 & 8u) != 0u;
        bool s01 = (a01 & 8u) != 0u;
        bool s10 = (a10 & 8u) != 0u;
        bool s11 = (a11 & 8u) != 0u;
        e000 = s00 ? make_float2(v00.z, v00.w) : make_float2(v00.x, v00.y);
        e100 = s00 ? make_float2(v00.x, v00.y) : make_float2(v00.z, v00.w);
        e001 = s01 ? make_float2(v01.z, v01.w) : make_float2(v01.x, v01.y);
        e101 = s01 ? make_float2(v01.x, v01.y) : make_float2(v01.z, v01.w);
        e010 = s10 ? make_float2(v10.z, v10.w) : make_float2(v10.x, v10.y);
        e110 = s10 ? make_float2(v10.x, v10.y) : make_float2(v10.z, v10.w);
        e011 = s11 ? make_float2(v11.z, v11.w) : make_float2(v11.x, v11.y);
        e111 = s11 ? make_float2(v11.x, v11.y) : make_float2(v11.z, v11.w);
    } else {
        unsigned hx1 = hx0 + 8u;
        e000 = __ldg((const float2*)(base + ((hx0 ^ a00) & MASK8)));
        e001 = __ldg((const float2*)(base + ((hx0 ^ a01) & MASK8)));
        e010 = __ldg((const float2*)(base + ((hx0 ^ a10) & MASK8)));
        e011 = __ldg((const float2*)(base + ((hx0 ^ a11) & MASK8)));
        e100 = __ldg((const float2*)(base + ((hx1 ^ a00) & MASK8)));
        e101 = __ldg((const float2*)(base + ((hx1 ^ a01) & MASK8)));
        e110 = __ldg((const float2*)(base + ((hx1 ^ a10) & MASK8)));
        e111 = __ldg((const float2*)(base + ((hx1 ^ a11) & MASK8)));
    }

    float2 c00 = lerp2(e000, e100, fx);
    float2 c01 = lerp2(e001, e101, fx);
    float2 c10 = lerp2(e010, e110, fx);
    float2 c11 = lerp2(e011, e111, fx);
    float2 c0  = lerp2(c00, c10, fy);
    float2 c1  = lerp2(c01, c11, fy);
    return lerp2(c0, c1, fz);
}

__device__ __forceinline__ int bucket_of(float px, float py, float pz) {
    int bx = min((int)(px * (float)BX), BX - 1);
    int by = min((int)(py * (float)BX), BX - 1);
    int bz = min((int)(pz * (float)BX), BX - 1);
    return (bz * BX + by) * BX + bx;
}

// ---- sort pipeline ----
__global__ void zero_hist_kernel() {
    unsigned i = blockIdx.x * blockDim.x + threadIdx.x;
    if (i < NBKT) g_hist[i] = 0u;
}

__global__ void hist_kernel(const float* __restrict__ x, unsigned npts) {
    unsigned i = blockIdx.x * blockDim.x + threadIdx.x;
    if (i >= npts) return;
    float px = x[3u * i], py = x[3u * i + 1u], pz = x[3u * i + 2u];
    atomicAdd(&g_hist[bucket_of(px, py, pz)], 1u);
}

// single block, 1024 threads, 32 buckets each (serial) + block scan.
// Writes exclusive bases into g_cursor (scatter consumes them).
__global__ void scan_kernel() {
    __shared__ unsigned s[1024];
    unsigned t = threadIdx.x;
    unsigned v[32];
    unsigned sum = 0u;
    #pragma unroll
    for (int j = 0; j < 32; j++) { v[j] = g_hist[32u * t + j]; sum += v[j]; }
    s[t] = sum;
    __syncthreads();
    for (unsigned off = 1u; off < 1024u; off <<= 1) {   // Hillis-Steele inclusive
        unsigned add = (t >= off) ? s[t - off] : 0u;
        __syncthreads();
        s[t] += add;
        __syncthreads();
    }
    unsigned run = s[t] - sum;                           // exclusive base
    #pragma unroll
    for (int j = 0; j < 32; j++) {
        g_cursor[32u * t + j] = run;
        run += v[j];
    }
}

// scatter writes ONLY perm (4B/pt) -> ~8x less random-write line traffic
// than scattering coords; encode re-gathers x via perm from L2-resident x.
__global__ void scatter_kernel(const float* __restrict__ x, unsigned npts) {
    unsigned i = blockIdx.x * blockDim.x + threadIdx.x;
    if (i >= npts) return;
    float px = x[3u * i], py = x[3u * i + 1u], pz = x[3u * i + 2u];
    unsigned pos = atomicAdd(&g_cursor[bucket_of(px, py, pz)], 1u);
    g_perm[pos] = i;
}

// ---- encode over the sorted order ----
// Warp = 16 consecutive sorted points x 2 half-threads. Lanes 0..15 run
// levels 0..7 on points p0..p15; lanes 16..31 run levels 8..15 on the same
// points. Every gather instruction has 16 lanes at the SAME level on
// spatially adjacent points -> cross-lane line merging at coarse levels.
__global__ void __launch_bounds__(256, 4) encode_sorted_kernel(
    const float* __restrict__ x,
    const float* __restrict__ emb,
    float* __restrict__ out,
    unsigned npts, Res16 rr)
{
    unsigned warp = threadIdx.x >> 5;
    unsigned lane = threadIdx.x & 31u;
    unsigned sub  = lane & 15u;
    unsigned half = lane >> 4;
    unsigned idx = blockIdx.x * 128u + warp * 16u + sub;   // sorted slot
    if (idx >= npts) return;

    unsigned pidx = g_perm[idx];
    float px = __ldg(x + 3u * pidx + 0u);
    float py = __ldg(x + 3u * pidx + 1u);
    float pz = __ldg(x + 3u * pidx + 2u);

    unsigned lvl0 = half * 8u;
    const char* base = (const char*)emb + (size_t)lvl0 * (size_t)(TBL * 8u);

    float2 f[8];
    #pragma unroll
    for (int j = 0; j < 8; j++) {
        f[j] = enc_level(base + (size_t)j * (size_t)(TBL * 8u),
                         px, py, pz, (float)rr.r[lvl0 + j]);
    }

    float* o = out + (size_t)pidx * 32u + half * 16u;
    *(float4*)(o +  0) = make_float4(f[0].x, f[0].y, f[1].x, f[1].y);
    *(float4*)(o +  4) = make_float4(f[2].x, f[2].y, f[3].x, f[3].y);
    *(float4*)(o +  8) = make_float4(f[4].x, f[4].y, f[5].x, f[5].y);
    *(float4*)(o + 12) = make_float4(f[6].x, f[6].y, f[7].x, f[7].y);
}

// ---- fallback (unsorted) for unexpected sizes ----
__global__ void __launch_bounds__(256, 4) hashenc_fallback_kernel(
    const float* __restrict__ x,
    const float* __restrict__ emb,
    float* __restrict__ out,
    unsigned npts, Res16 rr)
{
    unsigned tid = blockIdx.x * 256u + threadIdx.x;
    unsigned pt = tid >> 3;
    if (pt >= npts) return;
    unsigned chunk = tid & 7u;
    unsigned lvl = chunk * 2u;

    float px = __ldg(x + 3u * pt + 0u);
    float py = __ldg(x + 3u * pt + 1u);
    float pz = __ldg(x + 3u * pt + 2u);

    const char* base0 = (const char*)emb + (size_t)lvl * (size_t)(TBL * 8u);
    float r0 = (float)rr.r[lvl];
    float r1 = (float)rr.r[lvl + 1u];

    float2 f0 = enc_level(base0, px, py, pz, r0);
    float2 f1 = enc_level(base0 + (size_t)(TBL * 8u), px, py, pz, r1);

    float4 o = make_float4(f0.x, f0.y, f1.x, f1.y);
    *(float4*)(out + (size_t)pt * 32u + chunk * 4u) = o;
}

extern "C" void kernel_launch(void* const* d_in, const int* in_sizes, int n_in,
                              void* d_out, int out_size)
{
    const float* x   = (const float*)d_in[0];   // [2097152, 3] f32
    const float* emb = (const float*)d_in[1];   // [16, 524288, 2] f32
    float* out = (float*)d_out;                 // [2097152, 32] f32

    unsigned npts = (unsigned)(in_sizes[0] / 3);

    // Resolutions via the exact reference formula in double precision
    // (floor margins as small as 0.004 -> do NOT hardcode).
    Res16 rr;
    double b = exp((log(2048.0) - log(16.0)) / 15.0);
    for (int i = 0; i < 16; i++)
        rr.r[i] = (int)floor(16.0 * pow(b, (double)i));

    if (npts == NPTS) {
        unsigned blocks = (npts + 255u) / 256u;
        zero_hist_kernel<<<(NBKT + 255u) / 256u, 256>>>();
        hist_kernel<<<blocks, 256>>>(x, npts);
        scan_kernel<<<1, 1024>>>();
        scatter_kernel<<<blocks, 256>>>(x, npts);
        encode_sorted_kernel<<<(npts + 127u) / 128u, 256>>>(x, emb, out, npts, rr);
    } else {
        unsigned total = npts * 8u;
        hashenc_fallback_kernel<<<(total + 255u) / 256u, 256>>>(x, emb, out, npts, rr);
    }
}